// round 7
// baseline (speedup 1.0000x reference)
#include <cuda_runtime.h>
#include <cuda_fp16.h>
#include <cstdint>
#include <cmath>

#define NTOK 8192       // B*S
#define DDIM 1024
#define FDIM 4096
#define NEXP 4
#define NSLOT (NTOK * 2)
#define RPAD (NSLOT + 128 * NEXP)   // 16896

// ---------------- device scratch (module-load; no runtime alloc) ------------
__device__ int g_count[NEXP];
__device__ int g_list[NEXP][NTOK];
__device__ int g_off[NEXP + 1];
__device__ int g_rowslot[RPAD];
__device__ __half g_ahi[(size_t)RPAD * DDIM];
__device__ __half g_alo[(size_t)RPAD * DDIM];
__device__ __half g_h[(size_t)RPAD * FDIM];           // h as fp16
__device__ __half g_w1[(size_t)NEXP * FDIM * DDIM];   // [E][F][D] fp16(W1^T)
__device__ __half g_w2[(size_t)NEXP * DDIM * FDIM];   // [E][D][F] fp16(W2^T)
__device__ float g_y[(size_t)NSLOT * DDIM];

// ---------------- helpers ----------------------------------------------------
__device__ __forceinline__ uint32_t smem_u32(const void* p) {
    uint32_t a;
    asm("{ .reg .u64 t; cvta.to.shared.u64 t, %1; cvt.u32.u64 %0, t; }" : "=r"(a) : "l"(p));
    return a;
}
#define CP_ASYNC16(dst, src) \
    asm volatile("cp.async.cg.shared.global [%0], [%1], 16;" :: "r"(dst), "l"(src))
#define CP_COMMIT() asm volatile("cp.async.commit_group;" ::: "memory")
#define CP_WAIT1()  asm volatile("cp.async.wait_group 1;" ::: "memory")
#define CP_WAIT0()  asm volatile("cp.async.wait_group 0;" ::: "memory")

__device__ __forceinline__ void ldm_x4(uint32_t* r, uint32_t addr) {
    asm volatile("ldmatrix.sync.aligned.m8n8.x4.shared.b16 {%0,%1,%2,%3}, [%4];"
                 : "=r"(r[0]), "=r"(r[1]), "=r"(r[2]), "=r"(r[3]) : "r"(addr));
}
__device__ __forceinline__ void mma16816(float* c, const uint32_t* a, uint32_t b0, uint32_t b1) {
    asm volatile("mma.sync.aligned.m16n8k16.row.col.f32.f16.f16.f32 "
                 "{%0,%1,%2,%3}, {%4,%5,%6,%7}, {%8,%9}, {%0,%1,%2,%3};"
                 : "+f"(c[0]), "+f"(c[1]), "+f"(c[2]), "+f"(c[3])
                 : "r"(a[0]), "r"(a[1]), "r"(a[2]), "r"(a[3]), "r"(b0), "r"(b1));
}
__device__ __forceinline__ uint32_t pack2h(__half a, __half b) {
    return (uint32_t)__half_as_ushort(a) | ((uint32_t)__half_as_ushort(b) << 16);
}
__device__ __forceinline__ void split2h(float v, __half& h, __half& l) {
    h = __float2half(v);
    l = __float2half(v - __half2float(h));
}

// ---------------- small kernels ----------------------------------------------
__global__ void k_reset() { if (threadIdx.x < NEXP) g_count[threadIdx.x] = 0; }

__global__ void k_gate(const float* __restrict__ x, const float* __restrict__ Wg,
                       const float* __restrict__ bg) {
    int t = blockIdx.x, tid = threadIdx.x;
    const float* xr = x + (size_t)t * DDIM;
    float s0 = 0.f, s1 = 0.f, s2 = 0.f, s3 = 0.f;
    for (int i = tid; i < DDIM; i += 128) {
        float xv = xr[i];
        float4 w = *reinterpret_cast<const float4*>(Wg + (size_t)i * 4);
        s0 += xv * w.x; s1 += xv * w.y; s2 += xv * w.z; s3 += xv * w.w;
    }
    #pragma unroll
    for (int o = 16; o; o >>= 1) {
        s0 += __shfl_down_sync(~0u, s0, o); s1 += __shfl_down_sync(~0u, s1, o);
        s2 += __shfl_down_sync(~0u, s2, o); s3 += __shfl_down_sync(~0u, s3, o);
    }
    __shared__ float red[4][4];
    if ((tid & 31) == 0) { int w = tid >> 5; red[w][0]=s0; red[w][1]=s1; red[w][2]=s2; red[w][3]=s3; }
    __syncthreads();
    if (tid == 0) {
        float l[4];
        #pragma unroll
        for (int e = 0; e < 4; e++) l[e] = red[0][e]+red[1][e]+red[2][e]+red[3][e]+bg[e];
        int e0 = 0;
        #pragma unroll
        for (int e = 1; e < 4; e++) if (l[e] > l[e0]) e0 = e;
        int e1 = -1;
        #pragma unroll
        for (int e = 0; e < 4; e++) { if (e == e0) continue; if (e1 < 0 || l[e] > l[e1]) e1 = e; }
        int p0 = atomicAdd(&g_count[e0], 1); g_list[e0][p0] = t * 2;
        int p1 = atomicAdd(&g_count[e1], 1); g_list[e1][p1] = t * 2 + 1;
    }
}

__global__ void k_offsets() {
    if (threadIdx.x == 0) {
        int o = 0;
        for (int e = 0; e < NEXP; e++) { g_off[e] = o; o += (g_count[e] + 127) & ~127; }
        g_off[NEXP] = o;
    }
}

__global__ void k_pack(const float* __restrict__ x) {
    int b = blockIdx.x;
    if (b >= g_off[NEXP]) return;
    int e = 0;
    #pragma unroll
    for (int i = 1; i < NEXP; i++) if (b >= g_off[i]) e = i;
    int j = b - g_off[e];
    int tid = threadIdx.x;
    __half* dh = g_ahi + (size_t)b * DDIM;
    __half* dl = g_alo + (size_t)b * DDIM;
    if (j < g_count[e]) {
        int slot = g_list[e][j];
        if (tid == 0) g_rowslot[b] = slot;
        const float4* src = reinterpret_cast<const float4*>(x + (size_t)(slot >> 1) * DDIM);
        float4 v0 = src[tid * 2], v1 = src[tid * 2 + 1];
        float vv[8] = {v0.x, v0.y, v0.z, v0.w, v1.x, v1.y, v1.z, v1.w};
        __half hh[8], ll[8];
        #pragma unroll
        for (int q = 0; q < 8; q++) split2h(vv[q], hh[q], ll[q]);
        uint4 uh = make_uint4(pack2h(hh[0],hh[1]), pack2h(hh[2],hh[3]), pack2h(hh[4],hh[5]), pack2h(hh[6],hh[7]));
        uint4 ul = make_uint4(pack2h(ll[0],ll[1]), pack2h(ll[2],ll[3]), pack2h(ll[4],ll[5]), pack2h(ll[6],ll[7]));
        *reinterpret_cast<uint4*>(dh + tid * 8) = uh;
        *reinterpret_cast<uint4*>(dl + tid * 8) = ul;
    } else {
        if (tid == 0) g_rowslot[b] = -1;
        uint4 z = make_uint4(0, 0, 0, 0);
        *reinterpret_cast<uint4*>(dh + tid * 8) = z;
        *reinterpret_cast<uint4*>(dl + tid * 8) = z;
    }
}

// transpose: W [E][K][N] fp32 -> fp16 [E][N][K]
template <int K, int N>
__global__ void k_tr(const float* __restrict__ W, __half* __restrict__ hi) {
    __shared__ float t[32][33];
    int e = blockIdx.z;
    int nb = blockIdx.x * 32, kb = blockIdx.y * 32;
    int tx = threadIdx.x, ty = threadIdx.y;
    const float* src = W + (size_t)e * K * N;
    #pragma unroll
    for (int i = 0; i < 4; i++)
        t[ty + i * 8][tx] = src[(size_t)(kb + ty + i * 8) * N + nb + tx];
    __syncthreads();
    #pragma unroll
    for (int i = 0; i < 4; i++) {
        float v = t[tx][ty + i * 8];
        size_t idx = ((size_t)e * N + nb + ty + i * 8) * K + kb + tx;
        hi[idx] = __float2half(v);
    }
}

// ---------------- HMMA grouped GEMM ------------------------------------------
// C tile 128x128, warps 4x2 (each 32x64), K-chunk 64, 3-stage cp.async pipeline,
// ONE __syncthreads per chunk.
static constexpr int PITCH = 144;                // 128B data + 16B pad (conflict-free)
static constexpr int MATB  = 128 * PITCH;        // 18432

template <int KD, int ND, bool SWISH, bool TWOPASS>
__global__ void __launch_bounds__(256, 1)
k_mma(const __half* __restrict__ Ahi, const __half* __restrict__ Alo,
      const __half* __restrict__ Bhw, const float* __restrict__ bias) {
    constexpr int NMAT  = TWOPASS ? 3 : 2;
    constexpr int STAGE = NMAT * MATB;
    int row0 = blockIdx.x * 128;
    if (row0 >= g_off[NEXP]) return;
    int col0 = blockIdx.y * 128;
    int e = 0;
    #pragma unroll
    for (int i = 1; i < NEXP; i++) if (row0 >= g_off[i]) e = i;

    extern __shared__ char smc[];
    uint32_t sb = smem_u32(smc);
    float* sbias = reinterpret_cast<float*>(smc + 3 * STAGE);

    int tid = threadIdx.x, lid = tid & 31, wid = tid >> 5;
    int wm = wid >> 1, wn = wid & 1;

    if (tid < 128) sbias[tid] = bias[(size_t)e * ND + col0 + tid];

    const __half* Ah = Ahi + (size_t)row0 * KD;
    const __half* Al = TWOPASS ? (Alo + (size_t)row0 * KD) : nullptr;
    const __half* Bh = Bhw + ((size_t)e * ND + col0) * KD;

    // chunk = 128 rows x 64 halfs per matrix = 1024 x 16B per matrix
    auto copy_chunk = [&](uint32_t stage_base, int k0) {
        #pragma unroll
        for (int t = 0; t < NMAT * 4; t++) {
            int i = tid + t * 256;
            int mat = i >> 10, j = i & 1023;
            int r = j >> 3, c = j & 7;
            const __half* src;
            if (TWOPASS) src = (mat == 0 ? Ah : (mat == 1 ? Al : Bh)) + (size_t)r * KD + k0 + c * 8;
            else         src = (mat == 0 ? Ah : Bh) + (size_t)r * KD + k0 + c * 8;
            uint32_t dst = stage_base + mat * MATB + r * PITCH + c * 16;
            CP_ASYNC16(dst, src);
        }
    };

    float acc[2][8][4];
    #pragma unroll
    for (int a = 0; a < 2; a++)
        #pragma unroll
        for (int b = 0; b < 8; b++)
            #pragma unroll
            for (int q = 0; q < 4; q++) acc[a][b][q] = 0.f;

    const int NCH = KD / 64;
    copy_chunk(sb, 0); CP_COMMIT();
    copy_chunk(sb + STAGE, 64); CP_COMMIT();

    uint32_t lane_off = (uint32_t)((lid & 15) * PITCH + (lid >> 4) * 16);
    const uint32_t boff = (NMAT - 1) * MATB;

    int stg = 0;                                   // stage of chunk cch
    for (int cch = 0; cch < NCH; cch++) {
        if (cch + 1 < NCH) { CP_WAIT1(); } else { CP_WAIT0(); }
        __syncthreads();   // chunk cch ready; all warps done with chunk cch-1
        if (cch + 2 < NCH) {
            int ns = stg + 2; if (ns >= 3) ns -= 3;          // == (cch-1)%3, free
            copy_chunk(sb + ns * STAGE, (cch + 2) * 64);
            CP_COMMIT();
        }
        uint32_t st = sb + stg * STAGE;
        #pragma unroll
        for (int kt = 0; kt < 4; kt++) {
            uint32_t ah[2][4], al[2][4];
            #pragma unroll
            for (int mi = 0; mi < 2; mi++) {
                ldm_x4(ah[mi], st + (wm * 32 + mi * 16) * PITCH + kt * 32 + lane_off);
                if (TWOPASS)
                    ldm_x4(al[mi], st + MATB + (wm * 32 + mi * 16) * PITCH + kt * 32 + lane_off);
            }
            #pragma unroll
            for (int pr = 0; pr < 4; pr++) {
                uint32_t bfr[4];
                ldm_x4(bfr, st + boff + (wn * 64 + pr * 16) * PITCH + kt * 32 + lane_off);
                #pragma unroll
                for (int mi = 0; mi < 2; mi++) {
                    mma16816(acc[mi][pr * 2],     ah[mi], bfr[0], bfr[2]);
                    mma16816(acc[mi][pr * 2 + 1], ah[mi], bfr[1], bfr[3]);
                    if (TWOPASS) {
                        mma16816(acc[mi][pr * 2],     al[mi], bfr[0], bfr[2]);
                        mma16816(acc[mi][pr * 2 + 1], al[mi], bfr[1], bfr[3]);
                    }
                }
            }
        }
        if (++stg == 3) stg = 0;
    }

    // ---- epilogue ----
    #pragma unroll
    for (int mi = 0; mi < 2; mi++) {
        #pragma unroll
        for (int ni = 0; ni < 8; ni++) {
            int ccol = wn * 64 + ni * 8 + (lid & 3) * 2;
            #pragma unroll
            for (int h = 0; h < 2; h++) {
                int lrow = wm * 32 + mi * 16 + (lid >> 2) + h * 8;
                int grow = row0 + lrow;
                float v0 = acc[mi][ni][h * 2]     + sbias[ccol];
                float v1 = acc[mi][ni][h * 2 + 1] + sbias[ccol + 1];
                if (SWISH) {
                    v0 = v0 / (1.0f + expf(-v0));
                    v1 = v1 / (1.0f + expf(-v1));
                    size_t idx = (size_t)grow * ND + col0 + ccol;
                    *reinterpret_cast<uint32_t*>(g_h + idx) =
                        pack2h(__float2half(v0), __float2half(v1));
                } else {
                    int slot = g_rowslot[grow];
                    if (slot >= 0) {
                        float* yp = g_y + (size_t)slot * DDIM + col0 + ccol;
                        yp[0] = v0; yp[1] = v1;
                    }
                }
            }
        }
    }
}

// out[t] = y[2t] + y[2t+1]
__global__ void k_combine(float* __restrict__ out) {
    int i = blockIdx.x * blockDim.x + threadIdx.x;
    if (i >= NTOK * DDIM / 4) return;
    int t = i >> 8, d = i & 255;
    const float4* y = reinterpret_cast<const float4*>(g_y);
    float4 a = y[(size_t)(2 * t) * 256 + d];
    float4 b = y[(size_t)(2 * t + 1) * 256 + d];
    reinterpret_cast<float4*>(out)[i] = make_float4(a.x + b.x, a.y + b.y, a.z + b.z, a.w + b.w);
}

// -----------------------------------------------------------------------------
extern "C" void kernel_launch(void* const* d_in, const int* in_sizes, int n_in,
                              void* d_out, int out_size) {
    const float* x  = (const float*)d_in[0];
    const float* Wg = (const float*)d_in[1];
    const float* bg = (const float*)d_in[2];
    const float* W1 = (const float*)d_in[3];
    const float* b1 = (const float*)d_in[4];
    const float* W2 = (const float*)d_in[5];
    const float* b2 = (const float*)d_in[6];
    float* out = (float*)d_out;

    __half *ahi, *alo, *hp, *w1p, *w2p;
    cudaGetSymbolAddress((void**)&ahi, g_ahi); cudaGetSymbolAddress((void**)&alo, g_alo);
    cudaGetSymbolAddress((void**)&hp, g_h);
    cudaGetSymbolAddress((void**)&w1p, g_w1);  cudaGetSymbolAddress((void**)&w2p, g_w2);

    constexpr int DSM1 = 3 * 3 * MATB + 512 + 16;   // 166 KB
    constexpr int DSM2 = 3 * 2 * MATB + 512 + 16;   // 111 KB
    cudaFuncSetAttribute(k_mma<DDIM, FDIM, true, true>,   cudaFuncAttributeMaxDynamicSharedMemorySize, DSM1);
    cudaFuncSetAttribute(k_mma<FDIM, DDIM, false, false>, cudaFuncAttributeMaxDynamicSharedMemorySize, DSM2);

    k_reset<<<1, 32>>>();
    k_gate<<<NTOK, 128>>>(x, Wg, bg);
    k_offsets<<<1, 32>>>();
    k_pack<<<RPAD, 128>>>(x);
    k_tr<DDIM, FDIM><<<dim3(FDIM / 32, DDIM / 32, NEXP), dim3(32, 8)>>>(W1, w1p);
    k_tr<FDIM, DDIM><<<dim3(DDIM / 32, FDIM / 32, NEXP), dim3(32, 8)>>>(W2, w2p);

    dim3 g1(RPAD / 128, FDIM / 128);   // (132, 32)
    k_mma<DDIM, FDIM, true, true><<<g1, 256, DSM1>>>(ahi, alo, w1p, b1);
    dim3 g2(RPAD / 128, DDIM / 128);   // (132, 8)
    k_mma<FDIM, DDIM, false, false><<<g2, 256, DSM2>>>(hp, nullptr, w2p, b2);

    int nvec = NTOK * DDIM / 4;
    k_combine<<<(nvec + 255) / 256, 256>>>(out);
}

// round 8
// speedup vs baseline: 1.0635x; 1.0635x over previous
#include <cuda_runtime.h>
#include <cuda_fp16.h>
#include <cstdint>
#include <cmath>

#define NTOK 8192       // B*S
#define DDIM 1024
#define FDIM 4096
#define NEXP 4
#define NSLOT (NTOK * 2)
#define RPAD (NSLOT + 128 * NEXP)   // 16896

// ---------------- device scratch (module-load; no runtime alloc) ------------
__device__ int g_count[NEXP];
__device__ int g_list[NEXP][NTOK];
__device__ int g_off[NEXP + 1];
__device__ int g_rowslot[RPAD];
__device__ __half g_ahi[(size_t)RPAD * DDIM];
__device__ __half g_alo[(size_t)RPAD * DDIM];
__device__ __half g_h[(size_t)RPAD * FDIM];           // h as fp16
__device__ __half g_w1[(size_t)NEXP * FDIM * DDIM];   // [E][F][D] fp16(W1^T)
__device__ __half g_w2[(size_t)NEXP * DDIM * FDIM];   // [E][D][F] fp16(W2^T)
__device__ float g_y[(size_t)NSLOT * DDIM];

// ---------------- helpers ----------------------------------------------------
__device__ __forceinline__ uint32_t smem_u32(const void* p) {
    uint32_t a;
    asm("{ .reg .u64 t; cvta.to.shared.u64 t, %1; cvt.u32.u64 %0, t; }" : "=r"(a) : "l"(p));
    return a;
}
#define CP_ASYNC16(dst, src) \
    asm volatile("cp.async.cg.shared.global [%0], [%1], 16;" :: "r"(dst), "l"(src))
#define CP_COMMIT() asm volatile("cp.async.commit_group;" ::: "memory")
#define CP_WAIT1()  asm volatile("cp.async.wait_group 1;" ::: "memory")
#define CP_WAIT0()  asm volatile("cp.async.wait_group 0;" ::: "memory")

__device__ __forceinline__ void ldm_x4(uint32_t* r, uint32_t addr) {
    asm volatile("ldmatrix.sync.aligned.m8n8.x4.shared.b16 {%0,%1,%2,%3}, [%4];"
                 : "=r"(r[0]), "=r"(r[1]), "=r"(r[2]), "=r"(r[3]) : "r"(addr));
}
// NOTE: non-volatile on purpose — pure register op, let ptxas schedule freely.
__device__ __forceinline__ void mma16816(float* c, const uint32_t* a, uint32_t b0, uint32_t b1) {
    asm("mma.sync.aligned.m16n8k16.row.col.f32.f16.f16.f32 "
        "{%0,%1,%2,%3}, {%4,%5,%6,%7}, {%8,%9}, {%0,%1,%2,%3};"
        : "+f"(c[0]), "+f"(c[1]), "+f"(c[2]), "+f"(c[3])
        : "r"(a[0]), "r"(a[1]), "r"(a[2]), "r"(a[3]), "r"(b0), "r"(b1));
}
__device__ __forceinline__ uint32_t pack2h(__half a, __half b) {
    return (uint32_t)__half_as_ushort(a) | ((uint32_t)__half_as_ushort(b) << 16);
}
__device__ __forceinline__ void split2h(float v, __half& h, __half& l) {
    h = __float2half(v);
    l = __float2half(v - __half2float(h));
}

// ---------------- small kernels ----------------------------------------------
__global__ void k_reset() { if (threadIdx.x < NEXP) g_count[threadIdx.x] = 0; }

__global__ void k_gate(const float* __restrict__ x, const float* __restrict__ Wg,
                       const float* __restrict__ bg) {
    int t = blockIdx.x, tid = threadIdx.x;
    const float* xr = x + (size_t)t * DDIM;
    float s0 = 0.f, s1 = 0.f, s2 = 0.f, s3 = 0.f;
    for (int i = tid; i < DDIM; i += 128) {
        float xv = xr[i];
        float4 w = *reinterpret_cast<const float4*>(Wg + (size_t)i * 4);
        s0 += xv * w.x; s1 += xv * w.y; s2 += xv * w.z; s3 += xv * w.w;
    }
    #pragma unroll
    for (int o = 16; o; o >>= 1) {
        s0 += __shfl_down_sync(~0u, s0, o); s1 += __shfl_down_sync(~0u, s1, o);
        s2 += __shfl_down_sync(~0u, s2, o); s3 += __shfl_down_sync(~0u, s3, o);
    }
    __shared__ float red[4][4];
    if ((tid & 31) == 0) { int w = tid >> 5; red[w][0]=s0; red[w][1]=s1; red[w][2]=s2; red[w][3]=s3; }
    __syncthreads();
    if (tid == 0) {
        float l[4];
        #pragma unroll
        for (int e = 0; e < 4; e++) l[e] = red[0][e]+red[1][e]+red[2][e]+red[3][e]+bg[e];
        int e0 = 0;
        #pragma unroll
        for (int e = 1; e < 4; e++) if (l[e] > l[e0]) e0 = e;
        int e1 = -1;
        #pragma unroll
        for (int e = 0; e < 4; e++) { if (e == e0) continue; if (e1 < 0 || l[e] > l[e1]) e1 = e; }
        int p0 = atomicAdd(&g_count[e0], 1); g_list[e0][p0] = t * 2;
        int p1 = atomicAdd(&g_count[e1], 1); g_list[e1][p1] = t * 2 + 1;
    }
}

__global__ void k_offsets() {
    if (threadIdx.x == 0) {
        int o = 0;
        for (int e = 0; e < NEXP; e++) { g_off[e] = o; o += (g_count[e] + 127) & ~127; }
        g_off[NEXP] = o;
    }
}

__global__ void k_pack(const float* __restrict__ x) {
    int b = blockIdx.x;
    if (b >= g_off[NEXP]) return;
    int e = 0;
    #pragma unroll
    for (int i = 1; i < NEXP; i++) if (b >= g_off[i]) e = i;
    int j = b - g_off[e];
    int tid = threadIdx.x;
    __half* dh = g_ahi + (size_t)b * DDIM;
    __half* dl = g_alo + (size_t)b * DDIM;
    if (j < g_count[e]) {
        int slot = g_list[e][j];
        if (tid == 0) g_rowslot[b] = slot;
        const float4* src = reinterpret_cast<const float4*>(x + (size_t)(slot >> 1) * DDIM);
        float4 v0 = src[tid * 2], v1 = src[tid * 2 + 1];
        float vv[8] = {v0.x, v0.y, v0.z, v0.w, v1.x, v1.y, v1.z, v1.w};
        __half hh[8], ll[8];
        #pragma unroll
        for (int q = 0; q < 8; q++) split2h(vv[q], hh[q], ll[q]);
        uint4 uh = make_uint4(pack2h(hh[0],hh[1]), pack2h(hh[2],hh[3]), pack2h(hh[4],hh[5]), pack2h(hh[6],hh[7]));
        uint4 ul = make_uint4(pack2h(ll[0],ll[1]), pack2h(ll[2],ll[3]), pack2h(ll[4],ll[5]), pack2h(ll[6],ll[7]));
        *reinterpret_cast<uint4*>(dh + tid * 8) = uh;
        *reinterpret_cast<uint4*>(dl + tid * 8) = ul;
    } else {
        if (tid == 0) g_rowslot[b] = -1;
        uint4 z = make_uint4(0, 0, 0, 0);
        *reinterpret_cast<uint4*>(dh + tid * 8) = z;
        *reinterpret_cast<uint4*>(dl + tid * 8) = z;
    }
}

// transpose: W [E][K][N] fp32 -> fp16 [E][N][K]
template <int K, int N>
__global__ void k_tr(const float* __restrict__ W, __half* __restrict__ hi) {
    __shared__ float t[32][33];
    int e = blockIdx.z;
    int nb = blockIdx.x * 32, kb = blockIdx.y * 32;
    int tx = threadIdx.x, ty = threadIdx.y;
    const float* src = W + (size_t)e * K * N;
    #pragma unroll
    for (int i = 0; i < 4; i++)
        t[ty + i * 8][tx] = src[(size_t)(kb + ty + i * 8) * N + nb + tx];
    __syncthreads();
    #pragma unroll
    for (int i = 0; i < 4; i++) {
        float v = t[tx][ty + i * 8];
        size_t idx = ((size_t)e * N + nb + ty + i * 8) * K + kb + tx;
        hi[idx] = __float2half(v);
    }
}

// ---------------- HMMA grouped GEMM ------------------------------------------
// C tile 128x128, warps 4x2 (each 32x64), K-chunk 32, 2-stage pipeline (R6 cfg),
// MMA reordered: all frags loaded first, then pass-ah over all 16 accs, then pass-al.
static constexpr int PITCH = 80;
static constexpr int MATB  = 128 * PITCH;        // 10240

template <int KD, int ND, bool SWISH, bool TWOPASS>
__global__ void __launch_bounds__(256, 1)
k_mma(const __half* __restrict__ Ahi, const __half* __restrict__ Alo,
      const __half* __restrict__ Bhw, const float* __restrict__ bias) {
    constexpr int NMAT  = TWOPASS ? 3 : 2;
    constexpr int STAGE = NMAT * MATB;
    int row0 = blockIdx.x * 128;
    if (row0 >= g_off[NEXP]) return;
    int col0 = blockIdx.y * 128;
    int e = 0;
    #pragma unroll
    for (int i = 1; i < NEXP; i++) if (row0 >= g_off[i]) e = i;

    extern __shared__ char smc[];
    uint32_t sb = smem_u32(smc);
    float* sbias = reinterpret_cast<float*>(smc + 2 * STAGE);

    int tid = threadIdx.x, lid = tid & 31, wid = tid >> 5;
    int wm = wid >> 1, wn = wid & 1;

    if (tid < 128) sbias[tid] = bias[(size_t)e * ND + col0 + tid];

    const __half* Ah = Ahi + (size_t)row0 * KD;
    const __half* Al = TWOPASS ? (Alo + (size_t)row0 * KD) : nullptr;
    const __half* Bh = Bhw + ((size_t)e * ND + col0) * KD;

    auto copy_chunk = [&](uint32_t stage_base, int k0) {
        #pragma unroll
        for (int t = 0; t < NMAT * 2; t++) {
            int i = tid + t * 256;
            int mat = i >> 9, j = i & 511;
            int r = j >> 2, c = j & 3;
            const __half* src;
            if (TWOPASS) src = (mat == 0 ? Ah : (mat == 1 ? Al : Bh)) + (size_t)r * KD + k0 + c * 8;
            else         src = (mat == 0 ? Ah : Bh) + (size_t)r * KD + k0 + c * 8;
            uint32_t dst = stage_base + mat * MATB + r * PITCH + c * 16;
            CP_ASYNC16(dst, src);
        }
    };

    float acc[2][8][4];
    #pragma unroll
    for (int a = 0; a < 2; a++)
        #pragma unroll
        for (int b = 0; b < 8; b++)
            #pragma unroll
            for (int q = 0; q < 4; q++) acc[a][b][q] = 0.f;

    const int NCH = KD / 32;
    copy_chunk(sb, 0); CP_COMMIT();
    copy_chunk(sb + STAGE, 32); CP_COMMIT();

    uint32_t lane_off = (uint32_t)((lid & 15) * PITCH + (lid >> 4) * 16);
    const uint32_t boff = (NMAT - 1) * MATB;

    for (int cch = 0; cch < NCH; cch++) {
        if (cch + 1 < NCH) { CP_WAIT1(); } else { CP_WAIT0(); }
        __syncthreads();
        uint32_t st = sb + (cch & 1) * STAGE;
        #pragma unroll
        for (int kt = 0; kt < 2; kt++) {
            // ---- load ALL fragments for this k16 step ----
            uint32_t ah[2][4], al[2][4], bfr[4][4];
            #pragma unroll
            for (int mi = 0; mi < 2; mi++) {
                ldm_x4(ah[mi], st + (wm * 32 + mi * 16) * PITCH + kt * 32 + lane_off);
                if (TWOPASS)
                    ldm_x4(al[mi], st + MATB + (wm * 32 + mi * 16) * PITCH + kt * 32 + lane_off);
            }
            #pragma unroll
            for (int pr = 0; pr < 4; pr++)
                ldm_x4(bfr[pr], st + boff + (wn * 64 + pr * 16) * PITCH + kt * 32 + lane_off);

            // ---- pass ah: touch all 16 accumulators once ----
            #pragma unroll
            for (int pr = 0; pr < 4; pr++)
                #pragma unroll
                for (int mi = 0; mi < 2; mi++) {
                    mma16816(acc[mi][pr * 2],     ah[mi], bfr[pr][0], bfr[pr][2]);
                    mma16816(acc[mi][pr * 2 + 1], ah[mi], bfr[pr][1], bfr[pr][3]);
                }
            // ---- pass al: RAW distance = 16 mma ----
            if (TWOPASS) {
                #pragma unroll
                for (int pr = 0; pr < 4; pr++)
                    #pragma unroll
                    for (int mi = 0; mi < 2; mi++) {
                        mma16816(acc[mi][pr * 2],     al[mi], bfr[pr][0], bfr[pr][2]);
                        mma16816(acc[mi][pr * 2 + 1], al[mi], bfr[pr][1], bfr[pr][3]);
                    }
            }
        }
        __syncthreads();
        if (cch + 2 < NCH) { copy_chunk(sb + (cch & 1) * STAGE, (cch + 2) * 32); CP_COMMIT(); }
    }

    // ---- epilogue ----
    #pragma unroll
    for (int mi = 0; mi < 2; mi++) {
        #pragma unroll
        for (int ni = 0; ni < 8; ni++) {
            int ccol = wn * 64 + ni * 8 + (lid & 3) * 2;
            #pragma unroll
            for (int h = 0; h < 2; h++) {
                int lrow = wm * 32 + mi * 16 + (lid >> 2) + h * 8;
                int grow = row0 + lrow;
                float v0 = acc[mi][ni][h * 2]     + sbias[ccol];
                float v1 = acc[mi][ni][h * 2 + 1] + sbias[ccol + 1];
                if (SWISH) {
                    v0 = v0 / (1.0f + expf(-v0));
                    v1 = v1 / (1.0f + expf(-v1));
                    size_t idx = (size_t)grow * ND + col0 + ccol;
                    *reinterpret_cast<uint32_t*>(g_h + idx) =
                        pack2h(__float2half(v0), __float2half(v1));
                } else {
                    int slot = g_rowslot[grow];
                    if (slot >= 0) {
                        float* yp = g_y + (size_t)slot * DDIM + col0 + ccol;
                        yp[0] = v0; yp[1] = v1;
                    }
                }
            }
        }
    }
}

// out[t] = y[2t] + y[2t+1]
__global__ void k_combine(float* __restrict__ out) {
    int i = blockIdx.x * blockDim.x + threadIdx.x;
    if (i >= NTOK * DDIM / 4) return;
    int t = i >> 8, d = i & 255;
    const float4* y = reinterpret_cast<const float4*>(g_y);
    float4 a = y[(size_t)(2 * t) * 256 + d];
    float4 b = y[(size_t)(2 * t + 1) * 256 + d];
    reinterpret_cast<float4*>(out)[i] = make_float4(a.x + b.x, a.y + b.y, a.z + b.z, a.w + b.w);
}

// -----------------------------------------------------------------------------
extern "C" void kernel_launch(void* const* d_in, const int* in_sizes, int n_in,
                              void* d_out, int out_size) {
    const float* x  = (const float*)d_in[0];
    const float* Wg = (const float*)d_in[1];
    const float* bg = (const float*)d_in[2];
    const float* W1 = (const float*)d_in[3];
    const float* b1 = (const float*)d_in[4];
    const float* W2 = (const float*)d_in[5];
    const float* b2 = (const float*)d_in[6];
    float* out = (float*)d_out;

    __half *ahi, *alo, *hp, *w1p, *w2p;
    cudaGetSymbolAddress((void**)&ahi, g_ahi); cudaGetSymbolAddress((void**)&alo, g_alo);
    cudaGetSymbolAddress((void**)&hp, g_h);
    cudaGetSymbolAddress((void**)&w1p, g_w1);  cudaGetSymbolAddress((void**)&w2p, g_w2);

    constexpr int DSM1 = 2 * 3 * MATB + 512 + 16;
    constexpr int DSM2 = 2 * 2 * MATB + 512 + 16;
    cudaFuncSetAttribute(k_mma<DDIM, FDIM, true, true>,   cudaFuncAttributeMaxDynamicSharedMemorySize, DSM1);
    cudaFuncSetAttribute(k_mma<FDIM, DDIM, false, false>, cudaFuncAttributeMaxDynamicSharedMemorySize, DSM2);

    k_reset<<<1, 32>>>();
    k_gate<<<NTOK, 128>>>(x, Wg, bg);
    k_offsets<<<1, 32>>>();
    k_pack<<<RPAD, 128>>>(x);
    k_tr<DDIM, FDIM><<<dim3(FDIM / 32, DDIM / 32, NEXP), dim3(32, 8)>>>(W1, w1p);
    k_tr<FDIM, DDIM><<<dim3(DDIM / 32, FDIM / 32, NEXP), dim3(32, 8)>>>(W2, w2p);

    dim3 g1(RPAD / 128, FDIM / 128);   // (132, 32)
    k_mma<DDIM, FDIM, true, true><<<g1, 256, DSM1>>>(ahi, alo, w1p, b1);
    dim3 g2(RPAD / 128, DDIM / 128);   // (132, 8)
    k_mma<FDIM, DDIM, false, false><<<g2, 256, DSM2>>>(hp, nullptr, w2p, b2);

    int nvec = NTOK * DDIM / 4;
    k_combine<<<(nvec + 255) / 256, 256>>>(out);
}

// round 9
// speedup vs baseline: 1.3834x; 1.3008x over previous
#include <cuda_runtime.h>
#include <cuda_fp16.h>
#include <cstdint>
#include <cmath>

#define NTOK 8192       // B*S
#define DDIM 1024
#define FDIM 4096
#define NEXP 4
#define NSLOT (NTOK * 2)
#define RPAD (NSLOT + 128 * NEXP)   // 16896

// ---------------- device scratch (module-load; no runtime alloc) ------------
__device__ int g_count[NEXP];
__device__ int g_list[NEXP][NTOK];
__device__ int g_off[NEXP + 1];
__device__ int g_rowslot[RPAD];
__device__ __half g_a[(size_t)RPAD * DDIM];           // packed x as fp16
__device__ __half g_h[(size_t)RPAD * FDIM];           // h as fp16
__device__ __half g_w1[(size_t)NEXP * FDIM * DDIM];   // [E][F][D] fp16(W1^T)
__device__ __half g_w2[(size_t)NEXP * DDIM * FDIM];   // [E][D][F] fp16(W2^T)
__device__ float g_y[(size_t)NSLOT * DDIM];

// ---------------- helpers ----------------------------------------------------
__device__ __forceinline__ uint32_t smem_u32(const void* p) {
    uint32_t a;
    asm("{ .reg .u64 t; cvta.to.shared.u64 t, %1; cvt.u32.u64 %0, t; }" : "=r"(a) : "l"(p));
    return a;
}
#define CP_ASYNC16(dst, src) \
    asm volatile("cp.async.cg.shared.global [%0], [%1], 16;" :: "r"(dst), "l"(src))
#define CP_COMMIT() asm volatile("cp.async.commit_group;" ::: "memory")
#define CP_WAIT1()  asm volatile("cp.async.wait_group 1;" ::: "memory")
#define CP_WAIT0()  asm volatile("cp.async.wait_group 0;" ::: "memory")

__device__ __forceinline__ void ldm_x4(uint32_t* r, uint32_t addr) {
    asm volatile("ldmatrix.sync.aligned.m8n8.x4.shared.b16 {%0,%1,%2,%3}, [%4];"
                 : "=r"(r[0]), "=r"(r[1]), "=r"(r[2]), "=r"(r[3]) : "r"(addr));
}
__device__ __forceinline__ void mma16816(float* c, const uint32_t* a, uint32_t b0, uint32_t b1) {
    asm("mma.sync.aligned.m16n8k16.row.col.f32.f16.f16.f32 "
        "{%0,%1,%2,%3}, {%4,%5,%6,%7}, {%8,%9}, {%0,%1,%2,%3};"
        : "+f"(c[0]), "+f"(c[1]), "+f"(c[2]), "+f"(c[3])
        : "r"(a[0]), "r"(a[1]), "r"(a[2]), "r"(a[3]), "r"(b0), "r"(b1));
}
__device__ __forceinline__ uint32_t pack2h(__half a, __half b) {
    return (uint32_t)__half_as_ushort(a) | ((uint32_t)__half_as_ushort(b) << 16);
}

// ---------------- small kernels ----------------------------------------------
__global__ void k_reset() { if (threadIdx.x < NEXP) g_count[threadIdx.x] = 0; }

__global__ void k_gate(const float* __restrict__ x, const float* __restrict__ Wg,
                       const float* __restrict__ bg) {
    int t = blockIdx.x, tid = threadIdx.x;
    const float* xr = x + (size_t)t * DDIM;
    float s0 = 0.f, s1 = 0.f, s2 = 0.f, s3 = 0.f;
    for (int i = tid; i < DDIM; i += 128) {
        float xv = xr[i];
        float4 w = *reinterpret_cast<const float4*>(Wg + (size_t)i * 4);
        s0 += xv * w.x; s1 += xv * w.y; s2 += xv * w.z; s3 += xv * w.w;
    }
    #pragma unroll
    for (int o = 16; o; o >>= 1) {
        s0 += __shfl_down_sync(~0u, s0, o); s1 += __shfl_down_sync(~0u, s1, o);
        s2 += __shfl_down_sync(~0u, s2, o); s3 += __shfl_down_sync(~0u, s3, o);
    }
    __shared__ float red[4][4];
    if ((tid & 31) == 0) { int w = tid >> 5; red[w][0]=s0; red[w][1]=s1; red[w][2]=s2; red[w][3]=s3; }
    __syncthreads();
    if (tid == 0) {
        float l[4];
        #pragma unroll
        for (int e = 0; e < 4; e++) l[e] = red[0][e]+red[1][e]+red[2][e]+red[3][e]+bg[e];
        int e0 = 0;
        #pragma unroll
        for (int e = 1; e < 4; e++) if (l[e] > l[e0]) e0 = e;
        int e1 = -1;
        #pragma unroll
        for (int e = 0; e < 4; e++) { if (e == e0) continue; if (e1 < 0 || l[e] > l[e1]) e1 = e; }
        int p0 = atomicAdd(&g_count[e0], 1); g_list[e0][p0] = t * 2;
        int p1 = atomicAdd(&g_count[e1], 1); g_list[e1][p1] = t * 2 + 1;
    }
}

__global__ void k_offsets() {
    if (threadIdx.x == 0) {
        int o = 0;
        for (int e = 0; e < NEXP; e++) { g_off[e] = o; o += (g_count[e] + 127) & ~127; }
        g_off[NEXP] = o;
    }
}

__global__ void k_pack(const float* __restrict__ x) {
    int b = blockIdx.x;
    if (b >= g_off[NEXP]) return;
    int e = 0;
    #pragma unroll
    for (int i = 1; i < NEXP; i++) if (b >= g_off[i]) e = i;
    int j = b - g_off[e];
    int tid = threadIdx.x;
    __half* dh = g_a + (size_t)b * DDIM;
    if (j < g_count[e]) {
        int slot = g_list[e][j];
        if (tid == 0) g_rowslot[b] = slot;
        const float4* src = reinterpret_cast<const float4*>(x + (size_t)(slot >> 1) * DDIM);
        float4 v0 = src[tid * 2], v1 = src[tid * 2 + 1];
        uint4 uh = make_uint4(
            pack2h(__float2half(v0.x), __float2half(v0.y)),
            pack2h(__float2half(v0.z), __float2half(v0.w)),
            pack2h(__float2half(v1.x), __float2half(v1.y)),
            pack2h(__float2half(v1.z), __float2half(v1.w)));
        *reinterpret_cast<uint4*>(dh + tid * 8) = uh;
    } else {
        if (tid == 0) g_rowslot[b] = -1;
        *reinterpret_cast<uint4*>(dh + tid * 8) = make_uint4(0, 0, 0, 0);
    }
}

// transpose: W [E][K][N] fp32 -> fp16 [E][N][K]
template <int K, int N>
__global__ void k_tr(const float* __restrict__ W, __half* __restrict__ hi) {
    __shared__ float t[32][33];
    int e = blockIdx.z;
    int nb = blockIdx.x * 32, kb = blockIdx.y * 32;
    int tx = threadIdx.x, ty = threadIdx.y;
    const float* src = W + (size_t)e * K * N;
    #pragma unroll
    for (int i = 0; i < 4; i++)
        t[ty + i * 8][tx] = src[(size_t)(kb + ty + i * 8) * N + nb + tx];
    __syncthreads();
    #pragma unroll
    for (int i = 0; i < 4; i++) {
        float v = t[tx][ty + i * 8];
        size_t idx = ((size_t)e * N + nb + ty + i * 8) * K + kb + tx;
        hi[idx] = __float2half(v);
    }
}

// ---------------- HMMA grouped GEMM (single-pass fp16) ------------------------
// C tile 128x128, warps 4x2 (each 32x64), K-chunk 32, 2-stage cp.async pipeline.
static constexpr int PITCH = 80;
static constexpr int MATB  = 128 * PITCH;        // 10240
static constexpr int STAGE = 2 * MATB;           // A | B
static constexpr int DSM   = 2 * STAGE + 512 + 16;

template <int KD, int ND, bool SWISH>
__global__ void __launch_bounds__(256, 1)
k_mma(const __half* __restrict__ Aw, const __half* __restrict__ Bw,
      const float* __restrict__ bias) {
    int row0 = blockIdx.x * 128;
    if (row0 >= g_off[NEXP]) return;
    int col0 = blockIdx.y * 128;
    int e = 0;
    #pragma unroll
    for (int i = 1; i < NEXP; i++) if (row0 >= g_off[i]) e = i;

    extern __shared__ char smc[];
    uint32_t sb = smem_u32(smc);
    float* sbias = reinterpret_cast<float*>(smc + 2 * STAGE);

    int tid = threadIdx.x, lid = tid & 31, wid = tid >> 5;
    int wm = wid >> 1, wn = wid & 1;

    if (tid < 128) sbias[tid] = bias[(size_t)e * ND + col0 + tid];

    const __half* Ah = Aw + (size_t)row0 * KD;
    const __half* Bh = Bw + ((size_t)e * ND + col0) * KD;

    auto copy_chunk = [&](uint32_t stage_base, int k0) {
        #pragma unroll
        for (int t = 0; t < 4; t++) {
            int i = tid + t * 256;
            int mat = i >> 9, j = i & 511;
            int r = j >> 2, c = j & 3;
            const __half* src = (mat == 0 ? Ah : Bh) + (size_t)r * KD + k0 + c * 8;
            uint32_t dst = stage_base + mat * MATB + r * PITCH + c * 16;
            CP_ASYNC16(dst, src);
        }
    };

    float acc[2][8][4];
    #pragma unroll
    for (int a = 0; a < 2; a++)
        #pragma unroll
        for (int b = 0; b < 8; b++)
            #pragma unroll
            for (int q = 0; q < 4; q++) acc[a][b][q] = 0.f;

    const int NCH = KD / 32;
    copy_chunk(sb, 0); CP_COMMIT();
    copy_chunk(sb + STAGE, 32); CP_COMMIT();

    uint32_t lane_off = (uint32_t)((lid & 15) * PITCH + (lid >> 4) * 16);

    for (int cch = 0; cch < NCH; cch++) {
        if (cch + 1 < NCH) { CP_WAIT1(); } else { CP_WAIT0(); }
        __syncthreads();
        uint32_t st = sb + (cch & 1) * STAGE;
        #pragma unroll
        for (int kt = 0; kt < 2; kt++) {
            uint32_t af[2][4], bfr[4][4];
            #pragma unroll
            for (int mi = 0; mi < 2; mi++)
                ldm_x4(af[mi], st + (wm * 32 + mi * 16) * PITCH + kt * 32 + lane_off);
            #pragma unroll
            for (int pr = 0; pr < 4; pr++)
                ldm_x4(bfr[pr], st + MATB + (wn * 64 + pr * 16) * PITCH + kt * 32 + lane_off);
            #pragma unroll
            for (int pr = 0; pr < 4; pr++)
                #pragma unroll
                for (int mi = 0; mi < 2; mi++) {
                    mma16816(acc[mi][pr * 2],     af[mi], bfr[pr][0], bfr[pr][2]);
                    mma16816(acc[mi][pr * 2 + 1], af[mi], bfr[pr][1], bfr[pr][3]);
                }
        }
        __syncthreads();
        if (cch + 2 < NCH) { copy_chunk(sb + (cch & 1) * STAGE, (cch + 2) * 32); CP_COMMIT(); }
    }

    // ---- epilogue ----
    #pragma unroll
    for (int mi = 0; mi < 2; mi++) {
        #pragma unroll
        for (int ni = 0; ni < 8; ni++) {
            int ccol = wn * 64 + ni * 8 + (lid & 3) * 2;
            #pragma unroll
            for (int h = 0; h < 2; h++) {
                int lrow = wm * 32 + mi * 16 + (lid >> 2) + h * 8;
                int grow = row0 + lrow;
                float v0 = acc[mi][ni][h * 2]     + sbias[ccol];
                float v1 = acc[mi][ni][h * 2 + 1] + sbias[ccol + 1];
                if (SWISH) {
                    v0 = v0 / (1.0f + expf(-v0));
                    v1 = v1 / (1.0f + expf(-v1));
                    size_t idx = (size_t)grow * ND + col0 + ccol;
                    *reinterpret_cast<uint32_t*>(g_h + idx) =
                        pack2h(__float2half(v0), __float2half(v1));
                } else {
                    int slot = g_rowslot[grow];
                    if (slot >= 0) {
                        float* yp = g_y + (size_t)slot * DDIM + col0 + ccol;
                        yp[0] = v0; yp[1] = v1;
                    }
                }
            }
        }
    }
}

// out[t] = y[2t] + y[2t+1]
__global__ void k_combine(float* __restrict__ out) {
    int i = blockIdx.x * blockDim.x + threadIdx.x;
    if (i >= NTOK * DDIM / 4) return;
    int t = i >> 8, d = i & 255;
    const float4* y = reinterpret_cast<const float4*>(g_y);
    float4 a = y[(size_t)(2 * t) * 256 + d];
    float4 b = y[(size_t)(2 * t + 1) * 256 + d];
    reinterpret_cast<float4*>(out)[i] = make_float4(a.x + b.x, a.y + b.y, a.z + b.z, a.w + b.w);
}

// -----------------------------------------------------------------------------
extern "C" void kernel_launch(void* const* d_in, const int* in_sizes, int n_in,
                              void* d_out, int out_size) {
    const float* x  = (const float*)d_in[0];
    const float* Wg = (const float*)d_in[1];
    const float* bg = (const float*)d_in[2];
    const float* W1 = (const float*)d_in[3];
    const float* b1 = (const float*)d_in[4];
    const float* W2 = (const float*)d_in[5];
    const float* b2 = (const float*)d_in[6];
    float* out = (float*)d_out;

    __half *ap, *hp, *w1p, *w2p;
    cudaGetSymbolAddress((void**)&ap, g_a);
    cudaGetSymbolAddress((void**)&hp, g_h);
    cudaGetSymbolAddress((void**)&w1p, g_w1);
    cudaGetSymbolAddress((void**)&w2p, g_w2);

    cudaFuncSetAttribute(k_mma<DDIM, FDIM, true>,  cudaFuncAttributeMaxDynamicSharedMemorySize, DSM);
    cudaFuncSetAttribute(k_mma<FDIM, DDIM, false>, cudaFuncAttributeMaxDynamicSharedMemorySize, DSM);

    k_reset<<<1, 32>>>();
    k_gate<<<NTOK, 128>>>(x, Wg, bg);
    k_offsets<<<1, 32>>>();
    k_pack<<<RPAD, 128>>>(x);
    k_tr<DDIM, FDIM><<<dim3(FDIM / 32, DDIM / 32, NEXP), dim3(32, 8)>>>(W1, w1p);
    k_tr<FDIM, DDIM><<<dim3(DDIM / 32, FDIM / 32, NEXP), dim3(32, 8)>>>(W2, w2p);

    dim3 g1(RPAD / 128, FDIM / 128);   // (132, 32)
    k_mma<DDIM, FDIM, true><<<g1, 256, DSM>>>(ap, w1p, b1);
    dim3 g2(RPAD / 128, DDIM / 128);   // (132, 8)
    k_mma<FDIM, DDIM, false><<<g2, 256, DSM>>>(hp, w2p, b2);

    int nvec = NTOK * DDIM / 4;
    k_combine<<<(nvec + 255) / 256, 256>>>(out);
}

// round 10
// speedup vs baseline: 1.3982x; 1.0107x over previous
#include <cuda_runtime.h>
#include <cuda_fp16.h>
#include <cstdint>
#include <cmath>

#define NTOK 8192       // B*S
#define DDIM 1024
#define FDIM 4096
#define NEXP 4
#define NSLOT (NTOK * 2)
#define RPAD (NSLOT + 128 * NEXP)   // 16896

// ---------------- device scratch (module-load; no runtime alloc) ------------
__device__ int g_count[NEXP];
__device__ int g_list[NEXP][NTOK];
__device__ int g_off[NEXP + 1];
__device__ int g_rowslot[RPAD];
__device__ __half g_a[(size_t)RPAD * DDIM];           // packed x as fp16
__device__ __half g_h[(size_t)RPAD * FDIM];           // h as fp16
__device__ __half g_w1[(size_t)NEXP * FDIM * DDIM];   // [E][F][D] fp16(W1^T)
__device__ __half g_w2[(size_t)NEXP * DDIM * FDIM];   // [E][D][F] fp16(W2^T)

// ---------------- helpers ----------------------------------------------------
__device__ __forceinline__ uint32_t smem_u32(const void* p) {
    uint32_t a;
    asm("{ .reg .u64 t; cvta.to.shared.u64 t, %1; cvt.u32.u64 %0, t; }" : "=r"(a) : "l"(p));
    return a;
}
#define CP_ASYNC16(dst, src) \
    asm volatile("cp.async.cg.shared.global [%0], [%1], 16;" :: "r"(dst), "l"(src))
#define CP_COMMIT() asm volatile("cp.async.commit_group;" ::: "memory")
#define CP_WAIT1()  asm volatile("cp.async.wait_group 1;" ::: "memory")
#define CP_WAIT0()  asm volatile("cp.async.wait_group 0;" ::: "memory")

__device__ __forceinline__ void ldm_x4(uint32_t* r, uint32_t addr) {
    asm volatile("ldmatrix.sync.aligned.m8n8.x4.shared.b16 {%0,%1,%2,%3}, [%4];"
                 : "=r"(r[0]), "=r"(r[1]), "=r"(r[2]), "=r"(r[3]) : "r"(addr));
}
__device__ __forceinline__ void mma16816(float* c, const uint32_t* a, uint32_t b0, uint32_t b1) {
    asm("mma.sync.aligned.m16n8k16.row.col.f32.f16.f16.f32 "
        "{%0,%1,%2,%3}, {%4,%5,%6,%7}, {%8,%9}, {%0,%1,%2,%3};"
        : "+f"(c[0]), "+f"(c[1]), "+f"(c[2]), "+f"(c[3])
        : "r"(a[0]), "r"(a[1]), "r"(a[2]), "r"(a[3]), "r"(b0), "r"(b1));
}
__device__ __forceinline__ uint32_t pack2h(__half a, __half b) {
    return (uint32_t)__half_as_ushort(a) | ((uint32_t)__half_as_ushort(b) << 16);
}

// ---------------- small kernels ----------------------------------------------
__global__ void k_reset() { if (threadIdx.x < NEXP) g_count[threadIdx.x] = 0; }

__global__ void k_zero(float* __restrict__ out) {
    int i = blockIdx.x * blockDim.x + threadIdx.x;
    if (i < NTOK * DDIM / 4)
        reinterpret_cast<float4*>(out)[i] = make_float4(0.f, 0.f, 0.f, 0.f);
}

__global__ void k_gate(const float* __restrict__ x, const float* __restrict__ Wg,
                       const float* __restrict__ bg) {
    int t = blockIdx.x, tid = threadIdx.x;
    const float* xr = x + (size_t)t * DDIM;
    float s0 = 0.f, s1 = 0.f, s2 = 0.f, s3 = 0.f;
    for (int i = tid; i < DDIM; i += 128) {
        float xv = xr[i];
        float4 w = *reinterpret_cast<const float4*>(Wg + (size_t)i * 4);
        s0 += xv * w.x; s1 += xv * w.y; s2 += xv * w.z; s3 += xv * w.w;
    }
    #pragma unroll
    for (int o = 16; o; o >>= 1) {
        s0 += __shfl_down_sync(~0u, s0, o); s1 += __shfl_down_sync(~0u, s1, o);
        s2 += __shfl_down_sync(~0u, s2, o); s3 += __shfl_down_sync(~0u, s3, o);
    }
    __shared__ float red[4][4];
    if ((tid & 31) == 0) { int w = tid >> 5; red[w][0]=s0; red[w][1]=s1; red[w][2]=s2; red[w][3]=s3; }
    __syncthreads();
    if (tid == 0) {
        float l[4];
        #pragma unroll
        for (int e = 0; e < 4; e++) l[e] = red[0][e]+red[1][e]+red[2][e]+red[3][e]+bg[e];
        int e0 = 0;
        #pragma unroll
        for (int e = 1; e < 4; e++) if (l[e] > l[e0]) e0 = e;
        int e1 = -1;
        #pragma unroll
        for (int e = 0; e < 4; e++) { if (e == e0) continue; if (e1 < 0 || l[e] > l[e1]) e1 = e; }
        int p0 = atomicAdd(&g_count[e0], 1); g_list[e0][p0] = t * 2;
        int p1 = atomicAdd(&g_count[e1], 1); g_list[e1][p1] = t * 2 + 1;
    }
}

__global__ void k_offsets() {
    if (threadIdx.x == 0) {
        int o = 0;
        for (int e = 0; e < NEXP; e++) { g_off[e] = o; o += (g_count[e] + 127) & ~127; }
        g_off[NEXP] = o;
    }
}

__global__ void k_pack(const float* __restrict__ x) {
    int b = blockIdx.x;
    if (b >= g_off[NEXP]) return;
    int e = 0;
    #pragma unroll
    for (int i = 1; i < NEXP; i++) if (b >= g_off[i]) e = i;
    int j = b - g_off[e];
    int tid = threadIdx.x;
    __half* dh = g_a + (size_t)b * DDIM;
    if (j < g_count[e]) {
        int slot = g_list[e][j];
        if (tid == 0) g_rowslot[b] = slot;
        const float4* src = reinterpret_cast<const float4*>(x + (size_t)(slot >> 1) * DDIM);
        float4 v0 = src[tid * 2], v1 = src[tid * 2 + 1];
        uint4 uh = make_uint4(
            pack2h(__float2half(v0.x), __float2half(v0.y)),
            pack2h(__float2half(v0.z), __float2half(v0.w)),
            pack2h(__float2half(v1.x), __float2half(v1.y)),
            pack2h(__float2half(v1.z), __float2half(v1.w)));
        *reinterpret_cast<uint4*>(dh + tid * 8) = uh;
    } else {
        if (tid == 0) g_rowslot[b] = -1;
        *reinterpret_cast<uint4*>(dh + tid * 8) = make_uint4(0, 0, 0, 0);
    }
}

// transpose: W [E][K][N] fp32 -> fp16 [E][N][K]
template <int K, int N>
__global__ void k_tr(const float* __restrict__ W, __half* __restrict__ hi) {
    __shared__ float t[32][33];
    int e = blockIdx.z;
    int nb = blockIdx.x * 32, kb = blockIdx.y * 32;
    int tx = threadIdx.x, ty = threadIdx.y;
    const float* src = W + (size_t)e * K * N;
    #pragma unroll
    for (int i = 0; i < 4; i++)
        t[ty + i * 8][tx] = src[(size_t)(kb + ty + i * 8) * N + nb + tx];
    __syncthreads();
    #pragma unroll
    for (int i = 0; i < 4; i++) {
        float v = t[tx][ty + i * 8];
        size_t idx = ((size_t)e * N + nb + ty + i * 8) * K + kb + tx;
        hi[idx] = __float2half(v);
    }
}

// ---------------- HMMA grouped GEMM (single-pass fp16, occ=2) ----------------
// C tile 128x128, warps 4x2 (each 32x64), K-chunk 32, 2-stage cp.async pipeline.
static constexpr int PITCH = 80;
static constexpr int MATB  = 128 * PITCH;        // 10240
static constexpr int STAGE = 2 * MATB;           // A | B
static constexpr int DSM   = 2 * STAGE + 512 + 16;   // ~41.5 KB -> 2 CTAs/SM

template <int KD, int ND, bool SWISH>
__global__ void __launch_bounds__(256, 2)
k_mma(const __half* __restrict__ Aw, const __half* __restrict__ Bw,
      const float* __restrict__ bias, float* __restrict__ out) {
    int row0 = blockIdx.x * 128;
    if (row0 >= g_off[NEXP]) return;
    int col0 = blockIdx.y * 128;
    int e = 0;
    #pragma unroll
    for (int i = 1; i < NEXP; i++) if (row0 >= g_off[i]) e = i;

    extern __shared__ char smc[];
    uint32_t sb = smem_u32(smc);
    float* sbias = reinterpret_cast<float*>(smc + 2 * STAGE);

    int tid = threadIdx.x, lid = tid & 31, wid = tid >> 5;
    int wm = wid >> 1, wn = wid & 1;

    if (tid < 128) sbias[tid] = bias[(size_t)e * ND + col0 + tid];

    const __half* Ah = Aw + (size_t)row0 * KD;
    const __half* Bh = Bw + ((size_t)e * ND + col0) * KD;

    auto copy_chunk = [&](uint32_t stage_base, int k0) {
        #pragma unroll
        for (int t = 0; t < 4; t++) {
            int i = tid + t * 256;
            int mat = i >> 9, j = i & 511;
            int r = j >> 2, c = j & 3;
            const __half* src = (mat == 0 ? Ah : Bh) + (size_t)r * KD + k0 + c * 8;
            uint32_t dst = stage_base + mat * MATB + r * PITCH + c * 16;
            CP_ASYNC16(dst, src);
        }
    };

    float acc[2][8][4];
    #pragma unroll
    for (int a = 0; a < 2; a++)
        #pragma unroll
        for (int b = 0; b < 8; b++)
            #pragma unroll
            for (int q = 0; q < 4; q++) acc[a][b][q] = 0.f;

    const int NCH = KD / 32;
    copy_chunk(sb, 0); CP_COMMIT();
    copy_chunk(sb + STAGE, 32); CP_COMMIT();

    uint32_t lane_off = (uint32_t)((lid & 15) * PITCH + (lid >> 4) * 16);

    for (int cch = 0; cch < NCH; cch++) {
        if (cch + 1 < NCH) { CP_WAIT1(); } else { CP_WAIT0(); }
        __syncthreads();
        uint32_t st = sb + (cch & 1) * STAGE;
        #pragma unroll
        for (int kt = 0; kt < 2; kt++) {
            uint32_t af[2][4], bfr[4][4];
            #pragma unroll
            for (int mi = 0; mi < 2; mi++)
                ldm_x4(af[mi], st + (wm * 32 + mi * 16) * PITCH + kt * 32 + lane_off);
            #pragma unroll
            for (int pr = 0; pr < 4; pr++)
                ldm_x4(bfr[pr], st + MATB + (wn * 64 + pr * 16) * PITCH + kt * 32 + lane_off);
            #pragma unroll
            for (int pr = 0; pr < 4; pr++)
                #pragma unroll
                for (int mi = 0; mi < 2; mi++) {
                    mma16816(acc[mi][pr * 2],     af[mi], bfr[pr][0], bfr[pr][2]);
                    mma16816(acc[mi][pr * 2 + 1], af[mi], bfr[pr][1], bfr[pr][3]);
                }
        }
        __syncthreads();
        if (cch + 2 < NCH) { copy_chunk(sb + (cch & 1) * STAGE, (cch + 2) * 32); CP_COMMIT(); }
    }

    // ---- epilogue ----
    #pragma unroll
    for (int mi = 0; mi < 2; mi++) {
        #pragma unroll
        for (int ni = 0; ni < 8; ni++) {
            int ccol = wn * 64 + ni * 8 + (lid & 3) * 2;
            #pragma unroll
            for (int h = 0; h < 2; h++) {
                int lrow = wm * 32 + mi * 16 + (lid >> 2) + h * 8;
                int grow = row0 + lrow;
                float v0 = acc[mi][ni][h * 2]     + sbias[ccol];
                float v1 = acc[mi][ni][h * 2 + 1] + sbias[ccol + 1];
                if (SWISH) {
                    v0 = v0 / (1.0f + expf(-v0));
                    v1 = v1 / (1.0f + expf(-v1));
                    size_t idx = (size_t)grow * ND + col0 + ccol;
                    *reinterpret_cast<uint32_t*>(g_h + idx) =
                        pack2h(__float2half(v0), __float2half(v1));
                } else {
                    int slot = g_rowslot[grow];
                    if (slot >= 0) {
                        // out[token] += y ; exactly two contributions per token,
                        // fp32 add is commutative -> deterministic result.
                        float* op = out + (size_t)(slot >> 1) * DDIM + col0 + ccol;
                        atomicAdd(op,     v0);
                        atomicAdd(op + 1, v1);
                    }
                }
            }
        }
    }
}

// -----------------------------------------------------------------------------
extern "C" void kernel_launch(void* const* d_in, const int* in_sizes, int n_in,
                              void* d_out, int out_size) {
    const float* x  = (const float*)d_in[0];
    const float* Wg = (const float*)d_in[1];
    const float* bg = (const float*)d_in[2];
    const float* W1 = (const float*)d_in[3];
    const float* b1 = (const float*)d_in[4];
    const float* W2 = (const float*)d_in[5];
    const float* b2 = (const float*)d_in[6];
    float* out = (float*)d_out;

    __half *ap, *hp, *w1p, *w2p;
    cudaGetSymbolAddress((void**)&ap, g_a);
    cudaGetSymbolAddress((void**)&hp, g_h);
    cudaGetSymbolAddress((void**)&w1p, g_w1);
    cudaGetSymbolAddress((void**)&w2p, g_w2);

    cudaFuncSetAttribute(k_mma<DDIM, FDIM, true>,  cudaFuncAttributeMaxDynamicSharedMemorySize, DSM);
    cudaFuncSetAttribute(k_mma<FDIM, DDIM, false>, cudaFuncAttributeMaxDynamicSharedMemorySize, DSM);

    k_reset<<<1, 32>>>();
    k_zero<<<(NTOK * DDIM / 4 + 255) / 256, 256>>>(out);
    k_gate<<<NTOK, 128>>>(x, Wg, bg);
    k_offsets<<<1, 32>>>();
    k_pack<<<RPAD, 128>>>(x);
    k_tr<DDIM, FDIM><<<dim3(FDIM / 32, DDIM / 32, NEXP), dim3(32, 8)>>>(W1, w1p);
    k_tr<FDIM, DDIM><<<dim3(DDIM / 32, FDIM / 32, NEXP), dim3(32, 8)>>>(W2, w2p);

    dim3 g1(RPAD / 128, FDIM / 128);   // (132, 32)
    k_mma<DDIM, FDIM, true><<<g1, 256, DSM>>>(ap, w1p, b1, nullptr);
    dim3 g2(RPAD / 128, DDIM / 128);   // (132, 8)
    k_mma<FDIM, DDIM, false><<<g2, 256, DSM>>>(hp, w2p, b2, out);
}

// round 11
// speedup vs baseline: 1.6633x; 1.1896x over previous
#include <cuda_runtime.h>
#include <cuda_fp16.h>
#include <cstdint>
#include <cmath>

#define NTOK 8192       // B*S
#define DDIM 1024
#define FDIM 4096
#define NEXP 4
#define NSLOT (NTOK * 2)
#define RPAD (NSLOT + 128 * NEXP)   // 16896

// ---------------- device scratch (module-load; no runtime alloc) ------------
__device__ int g_count[NEXP];
__device__ int g_list[NEXP][NTOK];
__device__ int g_off[NEXP + 1];
__device__ int g_rowslot[RPAD];
__device__ __half g_a[(size_t)RPAD * DDIM];           // packed x as fp16
__device__ __half g_h[(size_t)RPAD * FDIM];           // h as fp16
__device__ __half g_w1[(size_t)NEXP * DDIM * FDIM];   // [E][D][F] fp16(W1),原layout
__device__ __half g_w2[(size_t)NEXP * FDIM * DDIM];   // [E][F][D] fp16(W2), 原layout

// ---------------- helpers ----------------------------------------------------
__device__ __forceinline__ uint32_t smem_u32(const void* p) {
    uint32_t a;
    asm("{ .reg .u64 t; cvta.to.shared.u64 t, %1; cvt.u32.u64 %0, t; }" : "=r"(a) : "l"(p));
    return a;
}
#define CP_ASYNC16(dst, src) \
    asm volatile("cp.async.cg.shared.global [%0], [%1], 16;" :: "r"(dst), "l"(src))
#define CP_COMMIT() asm volatile("cp.async.commit_group;" ::: "memory")
#define CP_WAIT1()  asm volatile("cp.async.wait_group 1;" ::: "memory")
#define CP_WAIT0()  asm volatile("cp.async.wait_group 0;" ::: "memory")

__device__ __forceinline__ void ldm_x4(uint32_t* r, uint32_t addr) {
    asm volatile("ldmatrix.sync.aligned.m8n8.x4.shared.b16 {%0,%1,%2,%3}, [%4];"
                 : "=r"(r[0]), "=r"(r[1]), "=r"(r[2]), "=r"(r[3]) : "r"(addr));
}
__device__ __forceinline__ void ldm_x4_t(uint32_t* r, uint32_t addr) {
    asm volatile("ldmatrix.sync.aligned.m8n8.x4.trans.shared.b16 {%0,%1,%2,%3}, [%4];"
                 : "=r"(r[0]), "=r"(r[1]), "=r"(r[2]), "=r"(r[3]) : "r"(addr));
}
__device__ __forceinline__ void mma16816(float* c, const uint32_t* a, uint32_t b0, uint32_t b1) {
    asm("mma.sync.aligned.m16n8k16.row.col.f32.f16.f16.f32 "
        "{%0,%1,%2,%3}, {%4,%5,%6,%7}, {%8,%9}, {%0,%1,%2,%3};"
        : "+f"(c[0]), "+f"(c[1]), "+f"(c[2]), "+f"(c[3])
        : "r"(a[0]), "r"(a[1]), "r"(a[2]), "r"(a[3]), "r"(b0), "r"(b1));
}
__device__ __forceinline__ uint32_t pack2h(__half a, __half b) {
    return (uint32_t)__half_as_ushort(a) | ((uint32_t)__half_as_ushort(b) << 16);
}

// ---------------- small kernels ----------------------------------------------
__global__ void k_reset() { if (threadIdx.x < NEXP) g_count[threadIdx.x] = 0; }

__global__ void k_zero(float* __restrict__ out) {
    int i = blockIdx.x * blockDim.x + threadIdx.x;
    if (i < NTOK * DDIM / 4)
        reinterpret_cast<float4*>(out)[i] = make_float4(0.f, 0.f, 0.f, 0.f);
}

__global__ void k_gate(const float* __restrict__ x, const float* __restrict__ Wg,
                       const float* __restrict__ bg) {
    int t = blockIdx.x, tid = threadIdx.x;
    const float* xr = x + (size_t)t * DDIM;
    float s0 = 0.f, s1 = 0.f, s2 = 0.f, s3 = 0.f;
    for (int i = tid; i < DDIM; i += 128) {
        float xv = xr[i];
        float4 w = *reinterpret_cast<const float4*>(Wg + (size_t)i * 4);
        s0 += xv * w.x; s1 += xv * w.y; s2 += xv * w.z; s3 += xv * w.w;
    }
    #pragma unroll
    for (int o = 16; o; o >>= 1) {
        s0 += __shfl_down_sync(~0u, s0, o); s1 += __shfl_down_sync(~0u, s1, o);
        s2 += __shfl_down_sync(~0u, s2, o); s3 += __shfl_down_sync(~0u, s3, o);
    }
    __shared__ float red[4][4];
    if ((tid & 31) == 0) { int w = tid >> 5; red[w][0]=s0; red[w][1]=s1; red[w][2]=s2; red[w][3]=s3; }
    __syncthreads();
    if (tid == 0) {
        float l[4];
        #pragma unroll
        for (int e = 0; e < 4; e++) l[e] = red[0][e]+red[1][e]+red[2][e]+red[3][e]+bg[e];
        int e0 = 0;
        #pragma unroll
        for (int e = 1; e < 4; e++) if (l[e] > l[e0]) e0 = e;
        int e1 = -1;
        #pragma unroll
        for (int e = 0; e < 4; e++) { if (e == e0) continue; if (e1 < 0 || l[e] > l[e1]) e1 = e; }
        int p0 = atomicAdd(&g_count[e0], 1); g_list[e0][p0] = t * 2;
        int p1 = atomicAdd(&g_count[e1], 1); g_list[e1][p1] = t * 2 + 1;
    }
}

__global__ void k_offsets() {
    if (threadIdx.x == 0) {
        int o = 0;
        for (int e = 0; e < NEXP; e++) { g_off[e] = o; o += (g_count[e] + 127) & ~127; }
        g_off[NEXP] = o;
    }
}

__global__ void k_pack(const float* __restrict__ x) {
    int b = blockIdx.x;
    if (b >= g_off[NEXP]) return;
    int e = 0;
    #pragma unroll
    for (int i = 1; i < NEXP; i++) if (b >= g_off[i]) e = i;
    int j = b - g_off[e];
    int tid = threadIdx.x;
    __half* dh = g_a + (size_t)b * DDIM;
    if (j < g_count[e]) {
        int slot = g_list[e][j];
        if (tid == 0) g_rowslot[b] = slot;
        const float4* src = reinterpret_cast<const float4*>(x + (size_t)(slot >> 1) * DDIM);
        float4 v0 = src[tid * 2], v1 = src[tid * 2 + 1];
        uint4 uh = make_uint4(
            pack2h(__float2half(v0.x), __float2half(v0.y)),
            pack2h(__float2half(v0.z), __float2half(v0.w)),
            pack2h(__float2half(v1.x), __float2half(v1.y)),
            pack2h(__float2half(v1.z), __float2half(v1.w)));
        *reinterpret_cast<uint4*>(dh + tid * 8) = uh;
    } else {
        if (tid == 0) g_rowslot[b] = -1;
        *reinterpret_cast<uint4*>(dh + tid * 8) = make_uint4(0, 0, 0, 0);
    }
}

// elementwise convert fp32 -> fp16, layout preserved
__global__ void k_cvt(const float* __restrict__ src, __half* __restrict__ dst, int n4) {
    int i = blockIdx.x * blockDim.x + threadIdx.x;
    if (i < n4) {
        float4 v = reinterpret_cast<const float4*>(src)[i];
        uint2 o = make_uint2(pack2h(__float2half(v.x), __float2half(v.y)),
                             pack2h(__float2half(v.z), __float2half(v.w)));
        reinterpret_cast<uint2*>(dst)[i] = o;
    }
}

// ---------------- HMMA grouped GEMM (single-pass fp16, B row-major [K,N]) ----
// C tile 128x128, warps 4x2 (each 32x64), K-chunk 32, 2-stage cp.async pipeline.
// A smem: [128 m][32 k] pitch 80B (K-major, normal ldmatrix).
// B smem: [32 k][128 n]  pitch 272B (row-major, ldmatrix.trans).
static constexpr int PITCHA = 80;
static constexpr int MATA   = 128 * PITCHA;      // 10240
static constexpr int PITCHB = 272;               // 256B data + 16B pad
static constexpr int MATB   = 32 * PITCHB;       // 8704
static constexpr int STAGE  = MATA + MATB;       // 18944
static constexpr int DSM    = 2 * STAGE + 512 + 16;   // ~38.5 KB -> 2 CTAs/SM

template <int KD, int ND, bool SWISH>
__global__ void __launch_bounds__(256, 2)
k_mma(const __half* __restrict__ Aw, const __half* __restrict__ Bw,
      const float* __restrict__ bias, float* __restrict__ out) {
    int row0 = blockIdx.x * 128;
    if (row0 >= g_off[NEXP]) return;
    int col0 = blockIdx.y * 128;
    int e = 0;
    #pragma unroll
    for (int i = 1; i < NEXP; i++) if (row0 >= g_off[i]) e = i;

    extern __shared__ char smc[];
    uint32_t sb = smem_u32(smc);
    float* sbias = reinterpret_cast<float*>(smc + 2 * STAGE);

    int tid = threadIdx.x, lid = tid & 31, wid = tid >> 5;
    int wm = wid >> 1, wn = wid & 1;

    if (tid < 128) sbias[tid] = bias[(size_t)e * ND + col0 + tid];

    const __half* Ah = Aw + (size_t)row0 * KD;
    const __half* Bh = Bw + (size_t)e * KD * ND + col0;   // [K][N], row stride ND

    auto copy_chunk = [&](uint32_t stage_base, int k0) {
        #pragma unroll
        for (int t = 0; t < 4; t++) {
            int i = tid + t * 256;
            if (i < 512) {                     // A: 128 rows x 64B
                int r = i >> 2, c = i & 3;
                const __half* src = Ah + (size_t)r * KD + k0 + c * 8;
                CP_ASYNC16(stage_base + r * PITCHA + c * 16, src);
            } else {                           // B: 32 rows x 256B
                int j = i - 512;
                int r = j >> 4, c = j & 15;
                const __half* src = Bh + (size_t)(k0 + r) * ND + c * 8;
                CP_ASYNC16(stage_base + MATA + r * PITCHB + c * 16, src);
            }
        }
    };

    float acc[2][8][4];
    #pragma unroll
    for (int a = 0; a < 2; a++)
        #pragma unroll
        for (int b = 0; b < 8; b++)
            #pragma unroll
            for (int q = 0; q < 4; q++) acc[a][b][q] = 0.f;

    const int NCH = KD / 32;
    copy_chunk(sb, 0); CP_COMMIT();
    copy_chunk(sb + STAGE, 32); CP_COMMIT();

    uint32_t lane_off_a = (uint32_t)((lid & 15) * PITCHA + (lid >> 4) * 16);
    uint32_t lane_off_b = (uint32_t)((lid & 15) * PITCHB + (lid >> 4) * 16);

    for (int cch = 0; cch < NCH; cch++) {
        if (cch + 1 < NCH) { CP_WAIT1(); } else { CP_WAIT0(); }
        __syncthreads();
        uint32_t st = sb + (cch & 1) * STAGE;
        #pragma unroll
        for (int kt = 0; kt < 2; kt++) {
            uint32_t af[2][4], bfr[4][4];
            #pragma unroll
            for (int mi = 0; mi < 2; mi++)
                ldm_x4(af[mi], st + (wm * 32 + mi * 16) * PITCHA + kt * 32 + lane_off_a);
            #pragma unroll
            for (int pr = 0; pr < 4; pr++)
                ldm_x4_t(bfr[pr], st + MATA + kt * 16 * PITCHB
                                  + (wn * 64 + pr * 16) * 2 + lane_off_b);
            #pragma unroll
            for (int pr = 0; pr < 4; pr++)
                #pragma unroll
                for (int mi = 0; mi < 2; mi++) {
                    mma16816(acc[mi][pr * 2],     af[mi], bfr[pr][0], bfr[pr][1]);
                    mma16816(acc[mi][pr * 2 + 1], af[mi], bfr[pr][2], bfr[pr][3]);
                }
        }
        __syncthreads();
        if (cch + 2 < NCH) { copy_chunk(sb + (cch & 1) * STAGE, (cch + 2) * 32); CP_COMMIT(); }
    }

    // ---- epilogue ----
    #pragma unroll
    for (int mi = 0; mi < 2; mi++) {
        #pragma unroll
        for (int ni = 0; ni < 8; ni++) {
            int ccol = wn * 64 + ni * 8 + (lid & 3) * 2;
            #pragma unroll
            for (int h = 0; h < 2; h++) {
                int lrow = wm * 32 + mi * 16 + (lid >> 2) + h * 8;
                int grow = row0 + lrow;
                float v0 = acc[mi][ni][h * 2]     + sbias[ccol];
                float v1 = acc[mi][ni][h * 2 + 1] + sbias[ccol + 1];
                if (SWISH) {
                    v0 = v0 / (1.0f + expf(-v0));
                    v1 = v1 / (1.0f + expf(-v1));
                    size_t idx = (size_t)grow * ND + col0 + ccol;
                    *reinterpret_cast<uint32_t*>(g_h + idx) =
                        pack2h(__float2half(v0), __float2half(v1));
                } else {
                    int slot = g_rowslot[grow];
                    if (slot >= 0) {
                        // out[token] += y ; exactly two fp32 contributions per token,
                        // addition commutative -> deterministic.
                        float* op = out + (size_t)(slot >> 1) * DDIM + col0 + ccol;
                        atomicAdd(op,     v0);
                        atomicAdd(op + 1, v1);
                    }
                }
            }
        }
    }
}

// -----------------------------------------------------------------------------
extern "C" void kernel_launch(void* const* d_in, const int* in_sizes, int n_in,
                              void* d_out, int out_size) {
    const float* x  = (const float*)d_in[0];
    const float* Wg = (const float*)d_in[1];
    const float* bg = (const float*)d_in[2];
    const float* W1 = (const float*)d_in[3];
    const float* b1 = (const float*)d_in[4];
    const float* W2 = (const float*)d_in[5];
    const float* b2 = (const float*)d_in[6];
    float* out = (float*)d_out;

    __half *ap, *hp, *w1p, *w2p;
    cudaGetSymbolAddress((void**)&ap, g_a);
    cudaGetSymbolAddress((void**)&hp, g_h);
    cudaGetSymbolAddress((void**)&w1p, g_w1);
    cudaGetSymbolAddress((void**)&w2p, g_w2);

    cudaFuncSetAttribute(k_mma<DDIM, FDIM, true>,  cudaFuncAttributeMaxDynamicSharedMemorySize, DSM);
    cudaFuncSetAttribute(k_mma<FDIM, DDIM, false>, cudaFuncAttributeMaxDynamicSharedMemorySize, DSM);

    k_reset<<<1, 32>>>();
    k_zero<<<(NTOK * DDIM / 4 + 255) / 256, 256>>>(out);
    k_gate<<<NTOK, 128>>>(x, Wg, bg);
    k_offsets<<<1, 32>>>();
    k_pack<<<RPAD, 128>>>(x);

    int nw = NEXP * DDIM * FDIM / 4;   // 4.19M float4 per weight tensor
    k_cvt<<<(nw + 255) / 256, 256>>>(W1, w1p, nw);
    k_cvt<<<(nw + 255) / 256, 256>>>(W2, w2p, nw);

    dim3 g1(RPAD / 128, FDIM / 128);   // (132, 32)
    k_mma<DDIM, FDIM, true><<<g1, 256, DSM>>>(ap, w1p, b1, nullptr);
    dim3 g2(RPAD / 128, DDIM / 128);   // (132, 8)
    k_mma<FDIM, DDIM, false><<<g2, 256, DSM>>>(hp, w2p, b2, out);
}